// round 3
// baseline (speedup 1.0000x reference)
#include <cuda_runtime.h>

#define T_LEN 1024
#define B_LEN 256
#define EMB   512
#define ATT   128
#define NF    32

static __device__ float g_pq[B_LEN * ATT];

// ---------- packed f32x2 helpers ----------
__device__ __forceinline__ unsigned long long PK(float a, float b) {
    unsigned long long r;
    asm("mov.b64 %0,{%1,%2};" : "=l"(r) : "f"(a), "f"(b));
    return r;
}
__device__ __forceinline__ float2 UPK(unsigned long long u) {
    float2 v;
    asm("mov.b64 {%0,%1},%2;" : "=f"(v.x), "=f"(v.y) : "l"(u));
    return v;
}
__device__ __forceinline__ unsigned long long FMA2(unsigned long long a,
                                                   unsigned long long b,
                                                   unsigned long long c) {
    asm("fma.rn.f32x2 %0, %1, %2, %0;" : "+l"(c) : "l"(a), "l"(b));
    return c;
}
__device__ __forceinline__ unsigned long long ADD2(unsigned long long a,
                                                   unsigned long long b) {
    unsigned long long r;
    asm("add.rn.f32x2 %0, %1, %2;" : "=l"(r) : "l"(a), "l"(b));
    return r;
}

__device__ __forceinline__ float tanh_f(float x) {
    // tanh(x) = 1 - 2/(e^{2x}+1); robust at both saturations, abs err ~1e-7
    float e = __expf(2.0f * x);
    return 1.0f - __fdividef(2.0f, e + 1.0f);
}

// ---------- kernel 1: pq[b][a] = query[b] . w_query[a] ----------
__global__ __launch_bounds__(256) void pq_kernel(const float* __restrict__ q,
                                                 const float* __restrict__ wq) {
    __shared__ float qs[8][1024];
    int tid = threadIdx.x;
    int b0 = blockIdx.x * 8;
    for (int i = tid; i < 8 * 1024; i += 256)
        qs[i >> 10][i & 1023] = q[(size_t)b0 * 1024 + i];
    __syncthreads();
    int w = tid >> 5, lane = tid & 31;
    for (int ai = 0; ai < 16; ai++) {
        int a = w * 16 + ai;
        float acc[8];
#pragma unroll
        for (int bb = 0; bb < 8; bb++) acc[bb] = 0.f;
        const float* wqa = wq + (size_t)a * 1024;
        for (int m = 0; m < 32; m++) {
            float wv = wqa[m * 32 + lane];
#pragma unroll
            for (int bb = 0; bb < 8; bb++)
                acc[bb] += qs[bb][m * 32 + lane] * wv;
        }
#pragma unroll
        for (int bb = 0; bb < 8; bb++) {
            float s = acc[bb];
#pragma unroll
            for (int off = 16; off; off >>= 1)
                s += __shfl_xor_sync(0xffffffffu, s, off);
            if (lane == 0) g_pq[(b0 + bb) * ATT + a] = s;
        }
    }
}

// ---------- kernel 2: fused conv+linear+tanh+softmax+context, one block per b ----------
// dynamic smem layout (in 8-byte units where noted):
//   aw2  : 2*1056 ull  — padded attention-weights, duplicated pairs {x[i],x[i+1]}
//   wc2  : 32*63  ull  — conv weights duplicated {w,w}, stride 63 (conflict-free LDS.64)
//   wl2  : 32*64  ull  — loc-linear transposed, paired over a: {wll[2p][f],wll[2p+1][f]}
//   pq2  : 64 float2, v2 : 64 float2
//   cv2  : 8*4*32 float2 — per-warp conv results, pairs over t
//   e_sm : 1024 float, red : 64 float
#define SMEM_BYTES ((2112 + 2016 + 2048) * 8 + 64 * 8 + 64 * 8 + 1024 * 8 + 1024 * 4 + 64 * 4)

__global__ __launch_bounds__(256, 2) void attn_kernel(
    const float* __restrict__ memory, const float* __restrict__ pmem,
    const float* __restrict__ awcat, const unsigned char* __restrict__ mask,
    const float* __restrict__ wconv, const float* __restrict__ wll,
    const float* __restrict__ v, float* __restrict__ outC,
    float* __restrict__ outW) {
    extern __shared__ unsigned long long sm[];
    unsigned long long* aw2 = sm;               // 2112
    unsigned long long* wc2 = aw2 + 2112;       // 2016
    unsigned long long* wl2 = wc2 + 2016;       // 2048
    float2* pq2 = (float2*)(wl2 + 2048);        // 64
    float2* v2 = pq2 + 64;                      // 64
    float2* cv2 = v2 + 64;                      // 1024
    float* e_sm = (float*)(cv2 + 1024);         // 1024
    float* red = e_sm + T_LEN;                  // 64

    const int b = blockIdx.x, tid = threadIdx.x;
    const int w = tid >> 5, lane = tid & 31;

    // ---- stage shared operands ----
    const float* awb = awcat + (size_t)b * 2 * T_LEN;
    for (int i = tid; i < 2112; i += 256) {
        int c = (i < 1056) ? 0 : 1;
        int p = i - c * 1056;
        float x0 = (p >= 15 && p < 1039) ? awb[c * T_LEN + p - 15] : 0.f;
        float x1 = (p >= 14 && p < 1038) ? awb[c * T_LEN + p - 14] : 0.f;
        aw2[i] = PK(x0, x1);
    }
    for (int i = tid; i < 1984; i += 256) {
        int f = i / 62, m = i - f * 62;
        float x = wconv[i];
        wc2[f * 63 + m] = PK(x, x);
    }
    for (int i = tid; i < 2048; i += 256) {
        int f = i >> 6, p = i & 63;
        wl2[i] = PK(wll[(2 * p) * NF + f], wll[(2 * p + 1) * NF + f]);
    }
    if (tid < 64) {
        pq2[tid] = make_float2(g_pq[b * ATT + 2 * tid], g_pq[b * ATT + 2 * tid + 1]);
    } else if (tid < 128) {
        int p = tid - 64;
        v2[p] = make_float2(v[2 * p], v[2 * p + 1]);
    }
    __syncthreads();

    const unsigned long long* pm2 =
        (const unsigned long long*)(pmem + (size_t)b * T_LEN * ATT);
    const float2 pqa = pq2[lane], pqb = pq2[lane + 32];
    const unsigned long long pqau = PK(pqa.x, pqa.y), pqbu = PK(pqb.x, pqb.y);
    const float2 va = v2[lane], vb = v2[lane + 32];
    const float NEG_INF = __int_as_float(0xff800000);

    // ---- energies: 8 t's per warp-iteration, pairs over t & a ----
    for (int t0 = w * 8; t0 < T_LEN; t0 += 64) {
        unsigned long long cp0 = 0ull, cp1 = 0ull, cp2 = 0ull, cp3 = 0ull;
        {
            const unsigned long long* wcb = wc2 + lane * 63;
#pragma unroll
            for (int c = 0; c < 2; c++) {
                const unsigned long long* aw = aw2 + c * 1056 + t0;
#pragma unroll
                for (int k = 0; k < 31; k++) {
                    unsigned long long wv = wcb[c * 31 + k];
                    cp0 = FMA2(aw[k], wv, cp0);
                    cp1 = FMA2(aw[k + 2], wv, cp1);
                    cp2 = FMA2(aw[k + 4], wv, cp2);
                    cp3 = FMA2(aw[k + 6], wv, cp3);
                }
            }
        }
        cv2[w * 128 + 0 * 32 + lane] = UPK(cp0);
        cv2[w * 128 + 1 * 32 + lane] = UPK(cp1);
        cv2[w * 128 + 2 * 32 + lane] = UPK(cp2);
        cv2[w * 128 + 3 * 32 + lane] = UPK(cp3);
        __syncwarp();

        unsigned long long s[8][2];
#pragma unroll
        for (int tt = 0; tt < 8; tt++) {
            s[tt][0] = ADD2(pqau, pm2[(size_t)(t0 + tt) * 64 + lane]);
            s[tt][1] = ADD2(pqbu, pm2[(size_t)(t0 + tt) * 64 + 32 + lane]);
        }
#pragma unroll 8
        for (int f = 0; f < NF; f++) {
            unsigned long long w0 = wl2[f * 64 + lane];
            unsigned long long w1 = wl2[f * 64 + 32 + lane];
#pragma unroll
            for (int j = 0; j < 4; j++) {
                float2 cc = cv2[w * 128 + j * 32 + f];
                unsigned long long cX = PK(cc.x, cc.x);
                unsigned long long cY = PK(cc.y, cc.y);
                s[2 * j][0] = FMA2(cX, w0, s[2 * j][0]);
                s[2 * j][1] = FMA2(cX, w1, s[2 * j][1]);
                s[2 * j + 1][0] = FMA2(cY, w0, s[2 * j + 1][0]);
                s[2 * j + 1][1] = FMA2(cY, w1, s[2 * j + 1][1]);
            }
        }
        float e[8];
#pragma unroll
        for (int tt = 0; tt < 8; tt++) {
            float2 x0 = UPK(s[tt][0]), x1 = UPK(s[tt][1]);
            e[tt] = va.x * tanh_f(x0.x) + va.y * tanh_f(x0.y) +
                    vb.x * tanh_f(x1.x) + vb.y * tanh_f(x1.y);
        }
#pragma unroll
        for (int off = 16; off; off >>= 1) {
#pragma unroll
            for (int tt = 0; tt < 8; tt++)
                e[tt] += __shfl_xor_sync(0xffffffffu, e[tt], off);
        }
        if (lane == 0) {
            const unsigned char* mb = mask + (size_t)b * T_LEN + t0;
#pragma unroll
            for (int tt = 0; tt < 8; tt++)
                e_sm[t0 + tt] = mb[tt] ? NEG_INF : e[tt];
        }
        __syncwarp();
    }
    __syncthreads();

    // ---- softmax over T ----
    float mx = NEG_INF;
    for (int i = tid; i < T_LEN; i += 256) mx = fmaxf(mx, e_sm[i]);
#pragma unroll
    for (int off = 16; off; off >>= 1)
        mx = fmaxf(mx, __shfl_xor_sync(0xffffffffu, mx, off));
    if (lane == 0) red[w] = mx;
    __syncthreads();
    if (tid == 0) {
        float m = red[0];
        for (int i = 1; i < 8; i++) m = fmaxf(m, red[i]);
        red[8] = m;
    }
    __syncthreads();
    mx = red[8];
    float ls = 0.f;
    for (int i = tid; i < T_LEN; i += 256) {
        float ex = __expf(e_sm[i] - mx);
        e_sm[i] = ex;
        ls += ex;
    }
#pragma unroll
    for (int off = 16; off; off >>= 1)
        ls += __shfl_xor_sync(0xffffffffu, ls, off);
    if (lane == 0) red[16 + w] = ls;
    __syncthreads();
    if (tid == 0) {
        float s0 = 0.f;
        for (int i = 0; i < 8; i++) s0 += red[16 + i];
        red[24] = 1.0f / s0;
    }
    __syncthreads();
    float inv = red[24];
    float* oW = outW + (size_t)b * T_LEN;
    for (int i = tid; i < T_LEN; i += 256) {
        float wv = e_sm[i] * inv;
        e_sm[i] = wv;
        oW[i] = wv;
    }
    __syncthreads();

    // ---- context: ctx[d] = sum_t w[t]*memory[b,t,d], float2 per thread ----
    const unsigned long long* mem2 =
        (const unsigned long long*)(memory + (size_t)b * T_LEN * EMB);
    unsigned long long a0 = 0ull, a1 = 0ull, a2 = 0ull, a3 = 0ull;
    for (int t = 0; t < T_LEN; t += 4) {
        a0 = FMA2(PK(e_sm[t + 0], e_sm[t + 0]), mem2[(size_t)(t + 0) * 256 + tid], a0);
        a1 = FMA2(PK(e_sm[t + 1], e_sm[t + 1]), mem2[(size_t)(t + 1) * 256 + tid], a1);
        a2 = FMA2(PK(e_sm[t + 2], e_sm[t + 2]), mem2[(size_t)(t + 2) * 256 + tid], a2);
        a3 = FMA2(PK(e_sm[t + 3], e_sm[t + 3]), mem2[(size_t)(t + 3) * 256 + tid], a3);
    }
    a0 = ADD2(ADD2(a0, a1), ADD2(a2, a3));
    ((unsigned long long*)outC)[(size_t)b * 256 + tid] = a0;
}

extern "C" void kernel_launch(void* const* d_in, const int* in_sizes, int n_in,
                              void* d_out, int out_size) {
    const float* query = (const float*)d_in[0];
    const float* memory = (const float*)d_in[1];
    const float* pmem = (const float*)d_in[2];
    const float* awcat = (const float*)d_in[3];
    const unsigned char* mask = (const unsigned char*)d_in[4];
    const float* wq = (const float*)d_in[5];
    const float* wconv = (const float*)d_in[6];
    const float* wll = (const float*)d_in[7];
    const float* v = (const float*)d_in[8];

    float* outC = (float*)d_out;                 // (B, 512)
    float* outW = outC + (size_t)B_LEN * EMB;    // (B, T)

    cudaFuncSetAttribute(attn_kernel, cudaFuncAttributeMaxDynamicSharedMemorySize,
                         SMEM_BYTES);

    pq_kernel<<<32, 256>>>(query, wq);
    attn_kernel<<<B_LEN, 256, SMEM_BYTES>>>(memory, pmem, awcat, mask, wconv,
                                            wll, v, outC, outW);
}

// round 4
// speedup vs baseline: 1.3148x; 1.3148x over previous
#include <cuda_runtime.h>

#define T_LEN 1024
#define B_LEN 256
#define EMB   512
#define ATT   128
#define NF    32

// ---------- packed f32x2 helpers ----------
__device__ __forceinline__ unsigned long long PK(float a, float b) {
    unsigned long long r;
    asm("mov.b64 %0,{%1,%2};" : "=l"(r) : "f"(a), "f"(b));
    return r;
}
__device__ __forceinline__ float2 UPK(unsigned long long u) {
    float2 v;
    asm("mov.b64 {%0,%1},%2;" : "=f"(v.x), "=f"(v.y) : "l"(u));
    return v;
}
__device__ __forceinline__ unsigned long long FMA2(unsigned long long a,
                                                   unsigned long long b,
                                                   unsigned long long c) {
    asm("fma.rn.f32x2 %0, %1, %2, %0;" : "+l"(c) : "l"(a), "l"(b));
    return c;
}
__device__ __forceinline__ unsigned long long ADD2(unsigned long long a,
                                                   unsigned long long b) {
    unsigned long long r;
    asm("add.rn.f32x2 %0, %1, %2;" : "=l"(r) : "l"(a), "l"(b));
    return r;
}

__device__ __forceinline__ float tanh_f(float x) {
    float e = __expf(2.0f * x);
    return 1.0f - __fdividef(2.0f, e + 1.0f);
}

// ---------- fused kernel: pq + conv + linear + tanh + softmax + context ----------
// dynamic smem (8-byte units unless noted):
//   aw2 : 2*1056 ull  — padded attention-weights, duplicated pairs {x[i],x[i+1]}
//   wc2 : 32*63  ull  — conv weights duplicated {w,w}, stride 63 (conflict-free)
//   wl2 : 32*64  ull  — loc-linear, paired over a
//   v2  : 64 float2
//   cv2 : 8*8*32 float2 (16KB) — per-warp conv results (16 t's per round)
//   e_sm: 1024 float  (also reused as qs staging for pq)
//   red : 64 float
//   pq_s = first 128 floats of cv2 (consumed into regs before cv2 is written)
#define SMEM_BYTES ((2112 + 2016 + 2048) * 8 + 64 * 8 + 2048 * 8 + 1024 * 4 + 64 * 4)

__global__ __launch_bounds__(256, 2) void attn_kernel(
    const float* __restrict__ query, const float* __restrict__ memory,
    const float* __restrict__ pmem, const float* __restrict__ awcat,
    const unsigned char* __restrict__ mask, const float* __restrict__ wq,
    const float* __restrict__ wconv, const float* __restrict__ wll,
    const float* __restrict__ v, float* __restrict__ outC,
    float* __restrict__ outW) {
    extern __shared__ unsigned long long sm[];
    unsigned long long* aw2 = sm;               // 2112
    unsigned long long* wc2 = aw2 + 2112;       // 2016
    unsigned long long* wl2 = wc2 + 2016;       // 2048
    float2* v2 = (float2*)(wl2 + 2048);         // 64
    float2* cv2 = v2 + 64;                      // 2048 float2
    float* e_sm = (float*)(cv2 + 2048);         // 1024 float
    float* red = e_sm + T_LEN;                  // 64
    float* pq_s = (float*)cv2;                  // 128 floats (transient)
    float* qs = e_sm;                           // 1024 floats (transient)

    const int b = blockIdx.x, tid = threadIdx.x;
    const int w = tid >> 5, lane = tid & 31;

    // ---- stage shared operands ----
    const float* awb = awcat + (size_t)b * 2 * T_LEN;
    for (int i = tid; i < 2112; i += 256) {
        int c = (i < 1056) ? 0 : 1;
        int p = i - c * 1056;
        float x0 = (p >= 15 && p < 1039) ? awb[c * T_LEN + p - 15] : 0.f;
        float x1 = (p >= 14 && p < 1038) ? awb[c * T_LEN + p - 14] : 0.f;
        aw2[i] = PK(x0, x1);
    }
    for (int i = tid; i < 1984; i += 256) {
        int f = i / 62, m = i - f * 62;
        float x = wconv[i];
        wc2[f * 63 + m] = PK(x, x);
    }
    for (int i = tid; i < 2048; i += 256) {
        int f = i >> 6, p = i & 63;
        wl2[i] = PK(wll[(2 * p) * NF + f], wll[(2 * p + 1) * NF + f]);
    }
    if (tid < 64) v2[tid] = make_float2(v[2 * tid], v[2 * tid + 1]);
    for (int i = tid; i < 1024; i += 256) qs[i] = query[(size_t)b * 1024 + i];
    __syncthreads();

    // ---- pq: each warp computes 16 attention dims (pq[b][a] = q . wq[a]) ----
    {
        const unsigned long long* q2 = (const unsigned long long*)qs;
#pragma unroll 4
        for (int ai = 0; ai < 16; ai++) {
            int a = w * 16 + ai;
            const unsigned long long* wq2 =
                (const unsigned long long*)(wq + (size_t)a * 1024);
            unsigned long long acc = 0ull;
#pragma unroll
            for (int m = 0; m < 16; m++)
                acc = FMA2(q2[m * 32 + lane], wq2[m * 32 + lane], acc);
            float2 p = UPK(acc);
            float s = p.x + p.y;
#pragma unroll
            for (int off = 16; off; off >>= 1)
                s += __shfl_xor_sync(0xffffffffu, s, off);
            if (lane == 0) pq_s[a] = s;
        }
    }
    __syncthreads();
    const unsigned long long pqau = PK(pq_s[2 * lane], pq_s[2 * lane + 1]);
    const unsigned long long pqbu = PK(pq_s[64 + 2 * lane], pq_s[64 + 2 * lane + 1]);
    const float2 va = v2[lane], vb = v2[lane + 32];
    __syncthreads();  // pq_s consumed; cv2 region now writable

    const unsigned long long* pm2 =
        (const unsigned long long*)(pmem + (size_t)b * T_LEN * ATT);
    const float NEG_INF = __int_as_float(0xff800000);

    // ---- energies: 16 t's per warp-round (conv), 2 linear passes of 8 t's ----
    for (int t0 = w * 16; t0 < T_LEN; t0 += 128) {
        unsigned long long cp[8];
#pragma unroll
        for (int j = 0; j < 8; j++) cp[j] = 0ull;
        {
            const unsigned long long* wcb = wc2 + lane * 63;
#pragma unroll
            for (int c = 0; c < 2; c++) {
                const unsigned long long* aw = aw2 + c * 1056 + t0;
                unsigned long long r[15];
#pragma unroll
                for (int i = 0; i < 15; i++) r[i] = aw[i];
#pragma unroll
                for (int k = 0; k < 31; k++) {
                    unsigned long long wv = wcb[c * 31 + k];
#pragma unroll
                    for (int j = 0; j < 8; j++) cp[j] = FMA2(r[2 * j], wv, cp[j]);
                    if (k < 30) {
#pragma unroll
                        for (int i = 0; i < 14; i++) r[i] = r[i + 1];
                        r[14] = aw[k + 15];
                    }
                }
            }
        }
#pragma unroll
        for (int j = 0; j < 8; j++) cv2[w * 256 + j * 32 + lane] = UPK(cp[j]);
        __syncwarp();

#pragma unroll
        for (int half = 0; half < 2; half++) {
            const int tb = t0 + half * 8;
            unsigned long long s[8][2];
#pragma unroll
            for (int tt = 0; tt < 8; tt++) {
                s[tt][0] = ADD2(pqau, pm2[(size_t)(tb + tt) * 64 + lane]);
                s[tt][1] = ADD2(pqbu, pm2[(size_t)(tb + tt) * 64 + 32 + lane]);
            }
#pragma unroll 8
            for (int f = 0; f < NF; f++) {
                unsigned long long w0 = wl2[f * 64 + lane];
                unsigned long long w1 = wl2[f * 64 + 32 + lane];
#pragma unroll
                for (int j = 0; j < 4; j++) {
                    float2 cc = cv2[w * 256 + (half * 4 + j) * 32 + f];
                    unsigned long long cX = PK(cc.x, cc.x);
                    unsigned long long cY = PK(cc.y, cc.y);
                    s[2 * j][0] = FMA2(cX, w0, s[2 * j][0]);
                    s[2 * j][1] = FMA2(cX, w1, s[2 * j][1]);
                    s[2 * j + 1][0] = FMA2(cY, w0, s[2 * j + 1][0]);
                    s[2 * j + 1][1] = FMA2(cY, w1, s[2 * j + 1][1]);
                }
            }
            float e[8];
#pragma unroll
            for (int tt = 0; tt < 8; tt++) {
                float2 x0 = UPK(s[tt][0]), x1 = UPK(s[tt][1]);
                e[tt] = va.x * tanh_f(x0.x) + va.y * tanh_f(x0.y) +
                        vb.x * tanh_f(x1.x) + vb.y * tanh_f(x1.y);
            }
#pragma unroll
            for (int off = 16; off; off >>= 1) {
#pragma unroll
                for (int tt = 0; tt < 8; tt++)
                    e[tt] += __shfl_xor_sync(0xffffffffu, e[tt], off);
            }
            if (lane == 0) {
                const unsigned char* mb = mask + (size_t)b * T_LEN + tb;
#pragma unroll
                for (int tt = 0; tt < 8; tt++)
                    e_sm[tb + tt] = mb[tt] ? NEG_INF : e[tt];
            }
        }
        __syncwarp();
    }
    __syncthreads();

    // ---- softmax over T ----
    float mx = NEG_INF;
    for (int i = tid; i < T_LEN; i += 256) mx = fmaxf(mx, e_sm[i]);
#pragma unroll
    for (int off = 16; off; off >>= 1)
        mx = fmaxf(mx, __shfl_xor_sync(0xffffffffu, mx, off));
    if (lane == 0) red[w] = mx;
    __syncthreads();
    if (tid == 0) {
        float m = red[0];
        for (int i = 1; i < 8; i++) m = fmaxf(m, red[i]);
        red[8] = m;
    }
    __syncthreads();
    mx = red[8];
    float ls = 0.f;
    for (int i = tid; i < T_LEN; i += 256) {
        float ex = __expf(e_sm[i] - mx);
        e_sm[i] = ex;
        ls += ex;
    }
#pragma unroll
    for (int off = 16; off; off >>= 1)
        ls += __shfl_xor_sync(0xffffffffu, ls, off);
    if (lane == 0) red[16 + w] = ls;
    __syncthreads();
    if (tid == 0) {
        float s0 = 0.f;
        for (int i = 0; i < 8; i++) s0 += red[16 + i];
        red[24] = 1.0f / s0;
    }
    __syncthreads();
    float inv = red[24];
    float* oW = outW + (size_t)b * T_LEN;
    for (int i = tid; i < T_LEN; i += 256) {
        float wv = e_sm[i] * inv;
        e_sm[i] = wv;
        oW[i] = wv;
    }
    __syncthreads();

    // ---- context: 8 independent accumulators for MLP, streaming loads ----
    const unsigned long long* mem2 =
        (const unsigned long long*)(memory + (size_t)b * T_LEN * EMB);
    unsigned long long a[8];
#pragma unroll
    for (int u = 0; u < 8; u++) a[u] = 0ull;
    for (int t = 0; t < T_LEN; t += 8) {
#pragma unroll
        for (int u = 0; u < 8; u++) {
            float wt = e_sm[t + u];
            unsigned long long m = __ldcs(&mem2[(size_t)(t + u) * 256 + tid]);
            a[u] = FMA2(PK(wt, wt), m, a[u]);
        }
    }
    unsigned long long r0 = ADD2(ADD2(a[0], a[1]), ADD2(a[2], a[3]));
    unsigned long long r1 = ADD2(ADD2(a[4], a[5]), ADD2(a[6], a[7]));
    ((unsigned long long*)outC)[(size_t)b * 256 + tid] = ADD2(r0, r1);
}

extern "C" void kernel_launch(void* const* d_in, const int* in_sizes, int n_in,
                              void* d_out, int out_size) {
    const float* query = (const float*)d_in[0];
    const float* memory = (const float*)d_in[1];
    const float* pmem = (const float*)d_in[2];
    const float* awcat = (const float*)d_in[3];
    const unsigned char* mask = (const unsigned char*)d_in[4];
    const float* wq = (const float*)d_in[5];
    const float* wconv = (const float*)d_in[6];
    const float* wll = (const float*)d_in[7];
    const float* v = (const float*)d_in[8];

    float* outC = (float*)d_out;               // (B, 512)
    float* outW = outC + (size_t)B_LEN * EMB;  // (B, T)

    cudaFuncSetAttribute(attn_kernel, cudaFuncAttributeMaxDynamicSharedMemorySize,
                         SMEM_BYTES);
    attn_kernel<<<B_LEN, 256, SMEM_BYTES>>>(query, memory, pmem, awcat, mask, wq,
                                            wconv, wll, v, outC, outW);
}

// round 5
// speedup vs baseline: 1.3519x; 1.0282x over previous
#include <cuda_runtime.h>

#define T_LEN 1024
#define B_LEN 256
#define EMB   512
#define ATT   128
#define NF    32

// ---------- packed f32x2 helpers ----------
__device__ __forceinline__ unsigned long long PK(float a, float b) {
    unsigned long long r;
    asm("mov.b64 %0,{%1,%2};" : "=l"(r) : "f"(a), "f"(b));
    return r;
}
__device__ __forceinline__ float2 UPK(unsigned long long u) {
    float2 v;
    asm("mov.b64 {%0,%1},%2;" : "=f"(v.x), "=f"(v.y) : "l"(u));
    return v;
}
__device__ __forceinline__ unsigned long long FMA2(unsigned long long a,
                                                   unsigned long long b,
                                                   unsigned long long c) {
    asm("fma.rn.f32x2 %0, %1, %2, %0;" : "+l"(c) : "l"(a), "l"(b));
    return c;
}
__device__ __forceinline__ unsigned long long ADD2(unsigned long long a,
                                                   unsigned long long b) {
    unsigned long long r;
    asm("add.rn.f32x2 %0, %1, %2;" : "=l"(r) : "l"(a), "l"(b));
    return r;
}
__device__ __forceinline__ unsigned long long MUL2(unsigned long long a,
                                                   unsigned long long b) {
    unsigned long long r;
    asm("mul.rn.f32x2 %0, %1, %2;" : "=l"(r) : "l"(a), "l"(b));
    return r;
}

__device__ __forceinline__ float tanh_f(float x) {
    float e = __expf(2.0f * x);
    return 1.0f - __fdividef(2.0f, e + 1.0f);
}

// ---------- fused: pq + conv + linear + tanh + ONLINE softmax + context ----------
// smem:
//   aw2 : 2*1056 ull — padded attn-weights, duplicated pairs
//   wc2 : 32*63  ull — conv weights dup {w,w}, stride 63
//   wl2 : 32*64  ull — loc-linear paired over a
//   v2  : 64 float2
//   cv2 : 2048 float2 (16KB) — per-warp conv results (pq_s/qs overlay transient)
//   e_sm: 1024 float  — raw energies (kept for final outW pass)
//   wch : 128 float   — current chunk's unnormalized weights
//   red : 32 float    — reductions + running m/S state
#define SMEM_BYTES ((2112 + 2016 + 2048) * 8 + 64 * 8 + 2048 * 8 + 1024 * 4 + 128 * 4 + 32 * 4)

__global__ __launch_bounds__(256, 2) void attn_kernel(
    const float* __restrict__ query, const float* __restrict__ memory,
    const float* __restrict__ pmem, const float* __restrict__ awcat,
    const unsigned char* __restrict__ mask, const float* __restrict__ wq,
    const float* __restrict__ wconv, const float* __restrict__ wll,
    const float* __restrict__ v, float* __restrict__ outC,
    float* __restrict__ outW) {
    extern __shared__ unsigned long long sm[];
    unsigned long long* aw2 = sm;               // 2112
    unsigned long long* wc2 = aw2 + 2112;       // 2016
    unsigned long long* wl2 = wc2 + 2016;       // 2048
    float2* v2 = (float2*)(wl2 + 2048);         // 64
    float2* cv2 = v2 + 64;                      // 2048
    float* e_sm = (float*)(cv2 + 2048);         // 1024
    float* wch = e_sm + T_LEN;                  // 128
    float* red = wch + 128;                     // 32
    float* pq_s = (float*)cv2;                  // transient
    float* qs = e_sm;                           // transient

    const int b = blockIdx.x, tid = threadIdx.x;
    const int w = tid >> 5, lane = tid & 31;
    const float NEG_INF = __int_as_float(0xff800000);

    // ---- stage shared operands ----
    const float* awb = awcat + (size_t)b * 2 * T_LEN;
    for (int i = tid; i < 2112; i += 256) {
        int c = (i < 1056) ? 0 : 1;
        int p = i - c * 1056;
        float x0 = (p >= 15 && p < 1039) ? awb[c * T_LEN + p - 15] : 0.f;
        float x1 = (p >= 14 && p < 1038) ? awb[c * T_LEN + p - 14] : 0.f;
        aw2[i] = PK(x0, x1);
    }
    for (int i = tid; i < 1984; i += 256) {
        int f = i / 62, m = i - f * 62;
        float x = wconv[i];
        wc2[f * 63 + m] = PK(x, x);
    }
    for (int i = tid; i < 2048; i += 256) {
        int f = i >> 6, p = i & 63;
        wl2[i] = PK(wll[(2 * p) * NF + f], wll[(2 * p + 1) * NF + f]);
    }
    if (tid < 64) v2[tid] = make_float2(v[2 * tid], v[2 * tid + 1]);
    if (tid == 0) { red[8] = NEG_INF; red[25] = 0.f; }  // m_run, S_run
    for (int i = tid; i < 1024; i += 256) qs[i] = query[(size_t)b * 1024 + i];
    __syncthreads();

    // ---- pq: each warp computes 16 attention dims ----
    {
        const unsigned long long* q2 = (const unsigned long long*)qs;
#pragma unroll 4
        for (int ai = 0; ai < 16; ai++) {
            int a = w * 16 + ai;
            const unsigned long long* wq2 =
                (const unsigned long long*)(wq + (size_t)a * 1024);
            unsigned long long acc = 0ull;
#pragma unroll
            for (int m = 0; m < 16; m++)
                acc = FMA2(q2[m * 32 + lane], wq2[m * 32 + lane], acc);
            float2 p = UPK(acc);
            float s = p.x + p.y;
#pragma unroll
            for (int off = 16; off; off >>= 1)
                s += __shfl_xor_sync(0xffffffffu, s, off);
            if (lane == 0) pq_s[a] = s;
        }
    }
    __syncthreads();
    const unsigned long long pqau = PK(pq_s[2 * lane], pq_s[2 * lane + 1]);
    const unsigned long long pqbu = PK(pq_s[64 + 2 * lane], pq_s[64 + 2 * lane + 1]);
    const float2 va = v2[lane], vb = v2[lane + 32];
    __syncthreads();  // pq_s consumed; cv2 writable

    const unsigned long long* pm2 =
        (const unsigned long long*)(pmem + (size_t)b * T_LEN * ATT);
    const unsigned long long* mem2 =
        (const unsigned long long*)(memory + (size_t)b * T_LEN * EMB);

    unsigned long long acc[8];
#pragma unroll
    for (int u = 0; u < 8; u++) acc[u] = 0ull;

    // ---- 8 chunks of 128 t; rotated start so co-resident CTAs de-phase ----
    for (int r = 0; r < 8; r++) {
        const int rr = (r + b) & 7;
        const int tb = rr * 128;
        const int t0 = tb + w * 16;

        // -- energies for this warp's 16 t's --
        unsigned long long cp[8];
#pragma unroll
        for (int j = 0; j < 8; j++) cp[j] = 0ull;
        {
            const unsigned long long* wcb = wc2 + lane * 63;
#pragma unroll
            for (int c = 0; c < 2; c++) {
                const unsigned long long* aw = aw2 + c * 1056 + t0;
                unsigned long long rg[15];
#pragma unroll
                for (int i = 0; i < 15; i++) rg[i] = aw[i];
#pragma unroll
                for (int k = 0; k < 31; k++) {
                    unsigned long long wv = wcb[c * 31 + k];
#pragma unroll
                    for (int j = 0; j < 8; j++) cp[j] = FMA2(rg[2 * j], wv, cp[j]);
                    if (k < 30) {
#pragma unroll
                        for (int i = 0; i < 14; i++) rg[i] = rg[i + 1];
                        rg[14] = aw[k + 15];
                    }
                }
            }
        }
#pragma unroll
        for (int j = 0; j < 8; j++) cv2[w * 256 + j * 32 + lane] = UPK(cp[j]);
        __syncwarp();

#pragma unroll
        for (int half = 0; half < 2; half++) {
            const int tbb = t0 + half * 8;
            unsigned long long s[8][2];
#pragma unroll
            for (int tt = 0; tt < 8; tt++) {
                s[tt][0] = ADD2(pqau, __ldcs(&pm2[(size_t)(tbb + tt) * 64 + lane]));
                s[tt][1] = ADD2(pqbu, __ldcs(&pm2[(size_t)(tbb + tt) * 64 + 32 + lane]));
            }
#pragma unroll 8
            for (int f = 0; f < NF; f++) {
                unsigned long long w0 = wl2[f * 64 + lane];
                unsigned long long w1 = wl2[f * 64 + 32 + lane];
#pragma unroll
                for (int j = 0; j < 4; j++) {
                    float2 cc = cv2[w * 256 + (half * 4 + j) * 32 + f];
                    unsigned long long cX = PK(cc.x, cc.x);
                    unsigned long long cY = PK(cc.y, cc.y);
                    s[2 * j][0] = FMA2(cX, w0, s[2 * j][0]);
                    s[2 * j][1] = FMA2(cX, w1, s[2 * j][1]);
                    s[2 * j + 1][0] = FMA2(cY, w0, s[2 * j + 1][0]);
                    s[2 * j + 1][1] = FMA2(cY, w1, s[2 * j + 1][1]);
                }
            }
            float e[8];
#pragma unroll
            for (int tt = 0; tt < 8; tt++) {
                float2 x0 = UPK(s[tt][0]), x1 = UPK(s[tt][1]);
                e[tt] = va.x * tanh_f(x0.x) + va.y * tanh_f(x0.y) +
                        vb.x * tanh_f(x1.x) + vb.y * tanh_f(x1.y);
            }
#pragma unroll
            for (int off = 16; off; off >>= 1) {
#pragma unroll
                for (int tt = 0; tt < 8; tt++)
                    e[tt] += __shfl_xor_sync(0xffffffffu, e[tt], off);
            }
            if (lane == 0) {
                const unsigned char* mb = mask + (size_t)b * T_LEN + tbb;
#pragma unroll
                for (int tt = 0; tt < 8; tt++)
                    e_sm[tbb + tt] = mb[tt] ? NEG_INF : e[tt];
            }
        }
        __syncthreads();  // chunk energies visible

        // -- chunk max reduce (threads 0..127) --
        if (tid < 128) {
            float vv = e_sm[tb + tid];
#pragma unroll
            for (int off = 16; off; off >>= 1)
                vv = fmaxf(vv, __shfl_xor_sync(0xffffffffu, vv, off));
            if (lane == 0) red[tid >> 5] = vv;
        }
        __syncthreads();
        if (tid == 0) {
            float cm = fmaxf(fmaxf(red[0], red[1]), fmaxf(red[2], red[3]));
            float m_old = red[8];
            float m_new = fmaxf(m_old, cm);
            red[8] = m_new;
            red[9] = __expf(m_old - m_new);  // 0 on first chunk
        }
        __syncthreads();
        const float m_new = red[8];
        const float scale = red[9];
        if (tid < 128) {
            float wv = __expf(e_sm[tb + tid] - m_new);
            wch[tid] = wv;
#pragma unroll
            for (int off = 16; off; off >>= 1)
                wv += __shfl_xor_sync(0xffffffffu, wv, off);
            if (lane == 0) red[16 + (tid >> 5)] = wv;
        }
        // rescale accumulators
        {
            unsigned long long sc2 = PK(scale, scale);
#pragma unroll
            for (int u = 0; u < 8; u++) acc[u] = MUL2(acc[u], sc2);
        }
        __syncthreads();  // wch + sum partials visible
        if (tid == 0) {
            red[25] = red[25] * scale + red[16] + red[17] + red[18] + red[19];
        }

        // -- context partial for this chunk (streams 256KB of memory) --
        for (int tt = 0; tt < 128; tt += 8) {
#pragma unroll
            for (int u = 0; u < 8; u++) {
                float wt = wch[tt + u];
                unsigned long long mv =
                    __ldcs(&mem2[(size_t)(tb + tt + u) * 256 + tid]);
                acc[u] = FMA2(PK(wt, wt), mv, acc[u]);
            }
        }
        // no barrier here: next round's post-energies barrier orders wch reuse
    }
    __syncthreads();

    // ---- finalize ----
    if (tid == 0) red[24] = 1.0f / red[25];
    __syncthreads();
    const float inv = red[24];
    const float m_final = red[8];

    float* oW = outW + (size_t)b * T_LEN;
    for (int i = tid; i < T_LEN; i += 256)
        oW[i] = __expf(e_sm[i] - m_final) * inv;

    unsigned long long r0 = ADD2(ADD2(acc[0], acc[1]), ADD2(acc[2], acc[3]));
    unsigned long long r1 = ADD2(ADD2(acc[4], acc[5]), ADD2(acc[6], acc[7]));
    unsigned long long ctx = MUL2(ADD2(r0, r1), PK(inv, inv));
    ((unsigned long long*)outC)[(size_t)b * 256 + tid] = ctx;
}

extern "C" void kernel_launch(void* const* d_in, const int* in_sizes, int n_in,
                              void* d_out, int out_size) {
    const float* query = (const float*)d_in[0];
    const float* memory = (const float*)d_in[1];
    const float* pmem = (const float*)d_in[2];
    const float* awcat = (const float*)d_in[3];
    const unsigned char* mask = (const unsigned char*)d_in[4];
    const float* wq = (const float*)d_in[5];
    const float* wconv = (const float*)d_in[6];
    const float* wll = (const float*)d_in[7];
    const float* v = (const float*)d_in[8];

    float* outC = (float*)d_out;               // (B, 512)
    float* outW = outC + (size_t)B_LEN * EMB;  // (B, T)

    cudaFuncSetAttribute(attn_kernel, cudaFuncAttributeMaxDynamicSharedMemorySize,
                         SMEM_BYTES);
    attn_kernel<<<B_LEN, 256, SMEM_BYTES>>>(query, memory, pmem, awcat, mask, wq,
                                            wconv, wll, v, outC, outW);
}

// round 6
// speedup vs baseline: 1.3647x; 1.0095x over previous
#include <cuda_runtime.h>

#define T_LEN 1024
#define B_LEN 256
#define EMB   512
#define ATT   128
#define NF    32

// ---------- packed f32x2 helpers ----------
__device__ __forceinline__ unsigned long long PK(float a, float b) {
    unsigned long long r;
    asm("mov.b64 %0,{%1,%2};" : "=l"(r) : "f"(a), "f"(b));
    return r;
}
__device__ __forceinline__ float2 UPK(unsigned long long u) {
    float2 v;
    asm("mov.b64 {%0,%1},%2;" : "=f"(v.x), "=f"(v.y) : "l"(u));
    return v;
}
__device__ __forceinline__ unsigned long long FMA2(unsigned long long a,
                                                   unsigned long long b,
                                                   unsigned long long c) {
    asm("fma.rn.f32x2 %0, %1, %2, %0;" : "+l"(c) : "l"(a), "l"(b));
    return c;
}
__device__ __forceinline__ unsigned long long ADD2(unsigned long long a,
                                                   unsigned long long b) {
    unsigned long long r;
    asm("add.rn.f32x2 %0, %1, %2;" : "=l"(r) : "l"(a), "l"(b));
    return r;
}
__device__ __forceinline__ unsigned long long MUL2(unsigned long long a,
                                                   unsigned long long b) {
    unsigned long long r;
    asm("mul.rn.f32x2 %0, %1, %2;" : "=l"(r) : "l"(a), "l"(b));
    return r;
}

__device__ __forceinline__ float tanh_f(float x) {
    float e = __expf(2.0f * x);
    return 1.0f - __fdividef(2.0f, e + 1.0f);
}

// ---------- fused: pq + conv + linear + tanh + ONLINE softmax + context ----------
#define SMEM_BYTES ((2112 + 2016 + 2048) * 8 + 64 * 8 + 2048 * 8 + 1024 * 4 + 128 * 4 + 32 * 4)

__global__ __launch_bounds__(256, 2) void attn_kernel(
    const float* __restrict__ query, const float* __restrict__ memory,
    const float* __restrict__ pmem, const float* __restrict__ awcat,
    const unsigned char* __restrict__ mask, const float* __restrict__ wq,
    const float* __restrict__ wconv, const float* __restrict__ wll,
    const float* __restrict__ v, float* __restrict__ outC,
    float* __restrict__ outW) {
    extern __shared__ unsigned long long sm[];
    unsigned long long* aw2 = sm;               // 2112
    unsigned long long* wc2 = aw2 + 2112;       // 2016
    unsigned long long* wl2 = wc2 + 2016;       // 2048
    float2* v2 = (float2*)(wl2 + 2048);         // 64
    float2* cv2 = v2 + 64;                      // 2048
    float* e_sm = (float*)(cv2 + 2048);         // 1024
    float* wch = e_sm + T_LEN;                  // 128
    float* red = wch + 128;                     // 32
    float* pq_s = (float*)cv2;                  // transient
    float* qs = e_sm;                           // transient
    float4* scr = (float4*)cv2;                 // final-reduction scratch (post-loop)

    const int b = blockIdx.x, tid = threadIdx.x;
    const int w = tid >> 5, lane = tid & 31;
    const int d4 = tid & 127, par = tid >> 7;   // context mapping
    const float NEG_INF = __int_as_float(0xff800000);

    // ---- stage shared operands ----
    const float* awb = awcat + (size_t)b * 2 * T_LEN;
    for (int i = tid; i < 2112; i += 256) {
        int c = (i < 1056) ? 0 : 1;
        int p = i - c * 1056;
        float x0 = (p >= 15 && p < 1039) ? awb[c * T_LEN + p - 15] : 0.f;
        float x1 = (p >= 14 && p < 1038) ? awb[c * T_LEN + p - 14] : 0.f;
        aw2[i] = PK(x0, x1);
    }
    for (int i = tid; i < 1984; i += 256) {
        int f = i / 62, m = i - f * 62;
        float x = wconv[i];
        wc2[f * 63 + m] = PK(x, x);
    }
    for (int i = tid; i < 2048; i += 256) {
        int f = i >> 6, p = i & 63;
        wl2[i] = PK(wll[(2 * p) * NF + f], wll[(2 * p + 1) * NF + f]);
    }
    if (tid < 64) v2[tid] = make_float2(v[2 * tid], v[2 * tid + 1]);
    if (tid == 0) { red[8] = NEG_INF; red[25] = 0.f; }  // m_run, S_run
    for (int i = tid; i < 1024; i += 256) qs[i] = query[(size_t)b * 1024 + i];
    __syncthreads();

    // ---- pq: each warp computes 16 attention dims ----
    {
        const unsigned long long* q2 = (const unsigned long long*)qs;
#pragma unroll 4
        for (int ai = 0; ai < 16; ai++) {
            int a = w * 16 + ai;
            const unsigned long long* wq2 =
                (const unsigned long long*)(wq + (size_t)a * 1024);
            unsigned long long acc = 0ull;
#pragma unroll
            for (int m = 0; m < 16; m++)
                acc = FMA2(q2[m * 32 + lane], wq2[m * 32 + lane], acc);
            float2 p = UPK(acc);
            float s = p.x + p.y;
#pragma unroll
            for (int off = 16; off; off >>= 1)
                s += __shfl_xor_sync(0xffffffffu, s, off);
            if (lane == 0) pq_s[a] = s;
        }
    }
    __syncthreads();
    const unsigned long long pqau = PK(pq_s[2 * lane], pq_s[2 * lane + 1]);
    const unsigned long long pqbu = PK(pq_s[64 + 2 * lane], pq_s[64 + 2 * lane + 1]);
    const float2 va = v2[lane], vb = v2[lane + 32];
    __syncthreads();  // pq_s consumed; cv2 writable

    const unsigned long long* pm2 =
        (const unsigned long long*)(pmem + (size_t)b * T_LEN * ATT);
    const float4* mem4 = (const float4*)(memory + (size_t)b * T_LEN * EMB);

    unsigned long long a0 = 0ull, a1 = 0ull;  // ctx accumulators (4 dims/thread)

    // ---- 8 chunks of 128 t; rotated start so co-resident CTAs de-phase ----
    for (int r = 0; r < 8; r++) {
        const int rr = (r + b) & 7;
        const int tb = rr * 128;
        const int t0 = tb + w * 16;

        // -- energies for this warp's 16 t's --
        unsigned long long cp[8];
#pragma unroll
        for (int j = 0; j < 8; j++) cp[j] = 0ull;
        {
            const unsigned long long* wcb = wc2 + lane * 63;
#pragma unroll
            for (int c = 0; c < 2; c++) {
                const unsigned long long* aw = aw2 + c * 1056 + t0;
                unsigned long long rg[15];
#pragma unroll
                for (int i = 0; i < 15; i++) rg[i] = aw[i];
#pragma unroll
                for (int k = 0; k < 31; k++) {
                    unsigned long long wv = wcb[c * 31 + k];
#pragma unroll
                    for (int j = 0; j < 8; j++) cp[j] = FMA2(rg[2 * j], wv, cp[j]);
                    if (k < 30) {
#pragma unroll
                        for (int i = 0; i < 14; i++) rg[i] = rg[i + 1];
                        rg[14] = aw[k + 15];
                    }
                }
            }
        }
#pragma unroll
        for (int j = 0; j < 8; j++) cv2[w * 256 + j * 32 + lane] = UPK(cp[j]);
        __syncwarp();

#pragma unroll
        for (int half = 0; half < 2; half++) {
            const int tbb = t0 + half * 8;
            unsigned long long s[8][2];
#pragma unroll
            for (int tt = 0; tt < 8; tt++) {
                s[tt][0] = ADD2(pqau, __ldcs(&pm2[(size_t)(tbb + tt) * 64 + lane]));
                s[tt][1] = ADD2(pqbu, __ldcs(&pm2[(size_t)(tbb + tt) * 64 + 32 + lane]));
            }
#pragma unroll 8
            for (int f = 0; f < NF; f++) {
                unsigned long long w0 = wl2[f * 64 + lane];
                unsigned long long w1 = wl2[f * 64 + 32 + lane];
#pragma unroll
                for (int j = 0; j < 4; j++) {
                    float2 cc = cv2[w * 256 + (half * 4 + j) * 32 + f];
                    unsigned long long cX = PK(cc.x, cc.x);
                    unsigned long long cY = PK(cc.y, cc.y);
                    s[2 * j][0] = FMA2(cX, w0, s[2 * j][0]);
                    s[2 * j][1] = FMA2(cX, w1, s[2 * j][1]);
                    s[2 * j + 1][0] = FMA2(cY, w0, s[2 * j + 1][0]);
                    s[2 * j + 1][1] = FMA2(cY, w1, s[2 * j + 1][1]);
                }
            }
            float e[8];
#pragma unroll
            for (int tt = 0; tt < 8; tt++) {
                float2 x0 = UPK(s[tt][0]), x1 = UPK(s[tt][1]);
                e[tt] = va.x * tanh_f(x0.x) + va.y * tanh_f(x0.y) +
                        vb.x * tanh_f(x1.x) + vb.y * tanh_f(x1.y);
            }
#pragma unroll
            for (int off = 16; off; off >>= 1) {
#pragma unroll
                for (int tt = 0; tt < 8; tt++)
                    e[tt] += __shfl_xor_sync(0xffffffffu, e[tt], off);
            }
            if (lane == 0) {
                const unsigned char* mb = mask + (size_t)b * T_LEN + tbb;
#pragma unroll
                for (int tt = 0; tt < 8; tt++)
                    e_sm[tbb + tt] = mb[tt] ? NEG_INF : e[tt];
            }
        }
        __syncthreads();  // chunk energies visible

        // -- chunk max reduce (threads 0..127) --
        if (tid < 128) {
            float vv = e_sm[tb + tid];
#pragma unroll
            for (int off = 16; off; off >>= 1)
                vv = fmaxf(vv, __shfl_xor_sync(0xffffffffu, vv, off));
            if (lane == 0) red[tid >> 5] = vv;
        }
        __syncthreads();
        if (tid == 0) {
            float cm = fmaxf(fmaxf(red[0], red[1]), fmaxf(red[2], red[3]));
            float m_old = red[8];
            float m_new = fmaxf(m_old, cm);
            red[8] = m_new;
            red[9] = __expf(m_old - m_new);  // 0 on first chunk
        }
        __syncthreads();
        const float m_new = red[8];
        const float scale = red[9];
        if (tid < 128) {
            float wv = __expf(e_sm[tb + tid] - m_new);
            wch[tid] = wv;
#pragma unroll
            for (int off = 16; off; off >>= 1)
                wv += __shfl_xor_sync(0xffffffffu, wv, off);
            if (lane == 0) red[16 + (tid >> 5)] = wv;
        }
        // rescale accumulators
        {
            unsigned long long sc2 = PK(scale, scale);
            a0 = MUL2(a0, sc2);
            a1 = MUL2(a1, sc2);
        }
        __syncthreads();  // wch + sum partials visible
        if (tid == 0) {
            red[25] = red[25] * scale + red[16] + red[17] + red[18] + red[19];
        }

        // -- context partial: LDG.128, 2 t-rows per instruction (parity split) --
        for (int tt = 0; tt < 128; tt += 16) {
            float4 mv[8];
#pragma unroll
            for (int u = 0; u < 8; u++)
                mv[u] = __ldcs(&mem4[(size_t)(tb + tt + 2 * u + par) * 128 + d4]);
            // L2-prefetch next 16-t window (clamped; harmless at the tail)
#pragma unroll
            for (int u = 0; u < 8; u++) {
                int tp = tb + tt + 16 + 2 * u + par;
                if (tp > T_LEN - 1) tp = T_LEN - 1;
                const float4* pf = &mem4[(size_t)tp * 128 + d4];
                asm volatile("prefetch.global.L2 [%0];" :: "l"(pf));
            }
#pragma unroll
            for (int u = 0; u < 8; u++) {
                float wt = wch[tt + 2 * u + par];
                unsigned long long w2 = PK(wt, wt);
                a0 = FMA2(w2, PK(mv[u].x, mv[u].y), a0);
                a1 = FMA2(w2, PK(mv[u].z, mv[u].w), a1);
            }
        }
        // no barrier: next round's post-energies barrier orders wch reuse
    }
    __syncthreads();

    // ---- finalize ----
    if (tid == 0) red[24] = 1.0f / red[25];
    // upper-parity threads park partials in scratch (cv2 free now)
    if (par == 1) {
        float2 x0 = UPK(a0), x1 = UPK(a1);
        scr[d4] = make_float4(x0.x, x0.y, x1.x, x1.y);
    }
    __syncthreads();
    const float inv = red[24];
    const float m_final = red[8];

    if (par == 0) {
        float4 o = scr[d4];
        float2 x0 = UPK(a0), x1 = UPK(a1);
        o.x = (o.x + x0.x) * inv;
        o.y = (o.y + x0.y) * inv;
        o.z = (o.z + x1.x) * inv;
        o.w = (o.w + x1.y) * inv;
        ((float4*)outC)[(size_t)b * 128 + d4] = o;
    }

    float* oW = outW + (size_t)b * T_LEN;
    for (int i = tid; i < T_LEN; i += 256)
        oW[i] = __expf(e_sm[i] - m_final) * inv;
}

extern "C" void kernel_launch(void* const* d_in, const int* in_sizes, int n_in,
                              void* d_out, int out_size) {
    const float* query = (const float*)d_in[0];
    const float* memory = (const float*)d_in[1];
    const float* pmem = (const float*)d_in[2];
    const float* awcat = (const float*)d_in[3];
    const unsigned char* mask = (const unsigned char*)d_in[4];
    const float* wq = (const float*)d_in[5];
    const float* wconv = (const float*)d_in[6];
    const float* wll = (const float*)d_in[7];
    const float* v = (const float*)d_in[8];

    float* outC = (float*)d_out;               // (B, 512)
    float* outW = outC + (size_t)B_LEN * EMB;  // (B, T)

    cudaFuncSetAttribute(attn_kernel, cudaFuncAttributeMaxDynamicSharedMemorySize,
                         SMEM_BYTES);
    attn_kernel<<<B_LEN, 256, SMEM_BYTES>>>(query, memory, pmem, awcat, mask, wq,
                                            wconv, wll, v, outC, outW);
}